// round 15
// baseline (speedup 1.0000x reference)
#include <cuda_runtime.h>
#include <cuda_bf16.h>
#include <cstdint>

// Problem constants
#define NNODES 50000
#define NEDGES 800000
#define FIN    128
#define HID    256
#define NGRAPH 128
#define NSCANB ((NNODES + 255) / 256)   // 196 scan blocks

// ---------------------------------------------------------------------------
// Scratch (static __device__ arrays; no allocation allowed)
// ---------------------------------------------------------------------------
__device__ __nv_bfloat16 d_AX[(size_t)NNODES * FIN];   // A @ X  (bf16)   [N,128]
__device__ __nv_bfloat16 d_H1[(size_t)NNODES * HID];   // relu(..) (bf16) [N,256]
__device__ float d_T2[(size_t)NNODES * HID];           // H1 @ W2 (fp32)  [N,256]
__device__ __nv_bfloat16 d_W1hi[FIN * HID];
__device__ __nv_bfloat16 d_W1lo[FIN * HID];
__device__ __nv_bfloat16 d_W2hi[HID * HID];
__device__ __nv_bfloat16 d_W2lo[HID * HID];
__device__ int   d_deg[NNODES];
__device__ int   d_rptr[NNODES + 1];
__device__ int   d_cursor[NNODES];
__device__ int   d_bsum[256];
__device__ int2  d_edge[NEDGES];                       // (src, w bits)
__device__ float d_G[NGRAPH * HID];                    // pooled graph features

// ---------------------------------------------------------------------------
// bf16 helpers
// ---------------------------------------------------------------------------
__device__ __forceinline__ uint32_t cvt2(float x, float y) {
    uint32_t h;
    asm("cvt.rn.bf16x2.f32 %0, %1, %2;" : "=r"(h) : "f"(y), "f"(x));  // lo16=x
    return h;
}
__device__ __forceinline__ void split2(float x, float y, uint32_t& hi, uint32_t& lo) {
    uint32_t h = cvt2(x, y);
    float hx = __uint_as_float(h << 16);
    float hy = __uint_as_float(h & 0xffff0000u);
    lo = cvt2(x - hx, y - hy);
    hi = h;
}

// ---------------------------------------------------------------------------
// 0. zero deg + G
// ---------------------------------------------------------------------------
__global__ void zero_kernel(int* deg, float* G) {
    int i = blockIdx.x * blockDim.x + threadIdx.x;
    if (i < NNODES) deg[i] = 0;
    if (i < NGRAPH * HID) G[i] = 0.0f;
}

// ---------------------------------------------------------------------------
// 0b. one-shot weight split: W1,W2 -> hi/lo bf16 planes
// ---------------------------------------------------------------------------
__global__ void split_w_kernel(const float* __restrict__ W1, const float* __restrict__ W2,
                               __nv_bfloat16* __restrict__ W1hi, __nv_bfloat16* __restrict__ W1lo,
                               __nv_bfloat16* __restrict__ W2hi, __nv_bfloat16* __restrict__ W2lo) {
    constexpr int NP1 = FIN * HID / 2;   // 16384 float2 pairs
    constexpr int NP2 = HID * HID / 2;   // 32768
    int i = blockIdx.x * blockDim.x + threadIdx.x;
    if (i < NP1) {
        float2 v = ((const float2*)W1)[i];
        uint32_t h, l; split2(v.x, v.y, h, l);
        ((uint32_t*)W1hi)[i] = h; ((uint32_t*)W1lo)[i] = l;
    } else if (i < NP1 + NP2) {
        int j = i - NP1;
        float2 v = ((const float2*)W2)[j];
        uint32_t h, l; split2(v.x, v.y, h, l);
        ((uint32_t*)W2hi)[j] = h; ((uint32_t*)W2lo)[j] = l;
    }
}

// ---------------------------------------------------------------------------
// 1. degree histogram over edge_dst
// ---------------------------------------------------------------------------
__global__ void hist_kernel(const int* __restrict__ dst, int* __restrict__ deg) {
    int e = blockIdx.x * blockDim.x + threadIdx.x;
    if (e < NEDGES) atomicAdd(&deg[dst[e]], 1);
}

// ---------------------------------------------------------------------------
// 2a. per-block exclusive prescan: pre[i] (in rptr), block totals in bsum
// ---------------------------------------------------------------------------
__global__ __launch_bounds__(256)
void scan_blocks(const int* __restrict__ deg, int* __restrict__ pre,
                 int* __restrict__ bsum) {
    __shared__ int ws[8];
    const int t = threadIdx.x, lane = t & 31, wid = t >> 5;
    const int i = blockIdx.x * 256 + t;
    int v = (i < NNODES) ? deg[i] : 0;
    int x = v;
    #pragma unroll
    for (int off = 1; off < 32; off <<= 1) {
        int y = __shfl_up_sync(0xffffffffu, x, off);
        if (lane >= off) x += y;
    }
    if (lane == 31) ws[wid] = x;
    __syncthreads();
    if (wid == 0) {
        int s = (lane < 8) ? ws[lane] : 0;
        #pragma unroll
        for (int off = 1; off < 8; off <<= 1) {
            int y = __shfl_up_sync(0xffffffffu, s, off);
            if (lane >= off) s += y;
        }
        if (lane < 8) ws[lane] = s;
    }
    __syncthreads();
    int incl = x + (wid > 0 ? ws[wid - 1] : 0);
    if (i < NNODES) pre[i] = incl - v;
    if (t == 255) bsum[blockIdx.x] = incl;
}

// ---------------------------------------------------------------------------
// 2b. scan the 196 block totals (one block); writes rptr[NNODES]
// ---------------------------------------------------------------------------
__global__ __launch_bounds__(256)
void scan_bsums(int* __restrict__ bsum, int* __restrict__ rptr) {
    __shared__ int ws[8];
    const int t = threadIdx.x, lane = t & 31, wid = t >> 5;
    int v = (t < NSCANB) ? bsum[t] : 0;
    int x = v;
    #pragma unroll
    for (int off = 1; off < 32; off <<= 1) {
        int y = __shfl_up_sync(0xffffffffu, x, off);
        if (lane >= off) x += y;
    }
    if (lane == 31) ws[wid] = x;
    __syncthreads();
    if (wid == 0) {
        int s = (lane < 8) ? ws[lane] : 0;
        #pragma unroll
        for (int off = 1; off < 8; off <<= 1) {
            int y = __shfl_up_sync(0xffffffffu, s, off);
            if (lane >= off) s += y;
        }
        if (lane < 8) ws[lane] = s;
    }
    __syncthreads();
    int incl = x + (wid > 0 ? ws[wid - 1] : 0);
    bsum[t] = incl - v;
    if (t == NSCANB - 1) rptr[NNODES] = incl;
}

// ---------------------------------------------------------------------------
// 2c. add block offsets in place; seed cursor
// ---------------------------------------------------------------------------
__global__ __launch_bounds__(256)
void add_offs(int* __restrict__ rptr, const int* __restrict__ bsum,
              int* __restrict__ cursor) {
    const int i = blockIdx.x * 256 + threadIdx.x;
    if (i < NNODES) {
        int r = rptr[i] + bsum[blockIdx.x];
        rptr[i] = r;
        cursor[i] = r;
    }
}

// ---------------------------------------------------------------------------
// 3. scatter edges into CSR slots (interleaved src+weight, one ST.64)
// ---------------------------------------------------------------------------
__global__ void fill_kernel(const int* __restrict__ src, const int* __restrict__ dst,
                            const float* __restrict__ w, int* __restrict__ cursor,
                            int2* __restrict__ edge) {
    int e = blockIdx.x * blockDim.x + threadIdx.x;
    if (e < NEDGES) {
        int d   = dst[e];
        int pos = atomicAdd(&cursor[d], 1);
        edge[pos] = make_int2(src[e], __float_as_int(w[e]));
    }
}

// ---------------------------------------------------------------------------
// 4. CSR gather spmm (fp32 gathers of x), bf16 packed output.
//    F4=32 threads per node, 8 nodes / block.
// ---------------------------------------------------------------------------
__global__ __launch_bounds__(256)
void spmm_csr_bf16out(const float4* __restrict__ X4,
                      const int* __restrict__ rptr,
                      const int2* __restrict__ E,
                      uint2* __restrict__ Yb) {
    constexpr int F4 = FIN / 4;           // 32
    constexpr int NPB = 256 / F4;         // 8
    const int g = threadIdx.x / F4;
    const int c = threadIdx.x % F4;
    const int d = blockIdx.x * NPB + g;
    if (d >= NNODES) return;
    const int b = rptr[d], e = rptr[d + 1];
    float4 acc = make_float4(0.f, 0.f, 0.f, 0.f);
    int i = b;
    for (; i + 4 <= e; i += 4) {
        int2 e0 = E[i], e1 = E[i + 1], e2 = E[i + 2], e3 = E[i + 3];
        float w0 = __int_as_float(e0.y), w1 = __int_as_float(e1.y);
        float w2 = __int_as_float(e2.y), w3 = __int_as_float(e3.y);
        float4 v0 = X4[(size_t)e0.x * F4 + c];
        float4 v1 = X4[(size_t)e1.x * F4 + c];
        float4 v2 = X4[(size_t)e2.x * F4 + c];
        float4 v3 = X4[(size_t)e3.x * F4 + c];
        acc.x = fmaf(w0, v0.x, acc.x); acc.y = fmaf(w0, v0.y, acc.y);
        acc.z = fmaf(w0, v0.z, acc.z); acc.w = fmaf(w0, v0.w, acc.w);
        acc.x = fmaf(w1, v1.x, acc.x); acc.y = fmaf(w1, v1.y, acc.y);
        acc.z = fmaf(w1, v1.z, acc.z); acc.w = fmaf(w1, v1.w, acc.w);
        acc.x = fmaf(w2, v2.x, acc.x); acc.y = fmaf(w2, v2.y, acc.y);
        acc.z = fmaf(w2, v2.z, acc.z); acc.w = fmaf(w2, v2.w, acc.w);
        acc.x = fmaf(w3, v3.x, acc.x); acc.y = fmaf(w3, v3.y, acc.y);
        acc.z = fmaf(w3, v3.z, acc.z); acc.w = fmaf(w3, v3.w, acc.w);
    }
    for (; i < e; i++) {
        int2 e0 = E[i];
        float w0 = __int_as_float(e0.y);
        float4 v0 = X4[(size_t)e0.x * F4 + c];
        acc.x = fmaf(w0, v0.x, acc.x); acc.y = fmaf(w0, v0.y, acc.y);
        acc.z = fmaf(w0, v0.z, acc.z); acc.w = fmaf(w0, v0.w, acc.w);
    }
    Yb[(size_t)d * F4 + c] = make_uint2(cvt2(acc.x, acc.y), cvt2(acc.z, acc.w));
}

// ---------------------------------------------------------------------------
// 7. spmm2 fused with bias+relu+global-sum-pool (fp32 float4 gathers)
// ---------------------------------------------------------------------------
__global__ __launch_bounds__(256)
void spmm_pool_v4(const float4* __restrict__ T4,
                  const int* __restrict__ rptr,
                  const int2* __restrict__ E,
                  const float4* __restrict__ b24,
                  const int* __restrict__ seg,
                  float* __restrict__ G) {
    constexpr int F4 = HID / 4;           // 64
    constexpr int NPB = 256 / F4;         // 4
    const int g = threadIdx.x / F4;
    const int c = threadIdx.x % F4;
    const int d = blockIdx.x * NPB + g;
    if (d >= NNODES) return;
    const int b = rptr[d], e = rptr[d + 1];
    float4 acc = make_float4(0.f, 0.f, 0.f, 0.f);
    int i = b;
    for (; i + 4 <= e; i += 4) {
        int2 e0 = E[i], e1 = E[i + 1], e2 = E[i + 2], e3 = E[i + 3];
        float w0 = __int_as_float(e0.y), w1 = __int_as_float(e1.y);
        float w2 = __int_as_float(e2.y), w3 = __int_as_float(e3.y);
        float4 v0 = T4[(size_t)e0.x * F4 + c];
        float4 v1 = T4[(size_t)e1.x * F4 + c];
        float4 v2 = T4[(size_t)e2.x * F4 + c];
        float4 v3 = T4[(size_t)e3.x * F4 + c];
        acc.x = fmaf(w0, v0.x, acc.x); acc.y = fmaf(w0, v0.y, acc.y);
        acc.z = fmaf(w0, v0.z, acc.z); acc.w = fmaf(w0, v0.w, acc.w);
        acc.x = fmaf(w1, v1.x, acc.x); acc.y = fmaf(w1, v1.y, acc.y);
        acc.z = fmaf(w1, v1.z, acc.z); acc.w = fmaf(w1, v1.w, acc.w);
        acc.x = fmaf(w2, v2.x, acc.x); acc.y = fmaf(w2, v2.y, acc.y);
        acc.z = fmaf(w2, v2.z, acc.z); acc.w = fmaf(w2, v2.w, acc.w);
        acc.x = fmaf(w3, v3.x, acc.x); acc.y = fmaf(w3, v3.y, acc.y);
        acc.z = fmaf(w3, v3.z, acc.z); acc.w = fmaf(w3, v3.w, acc.w);
    }
    for (; i < e; i++) {
        int2 e0 = E[i];
        float w0 = __int_as_float(e0.y);
        float4 v0 = T4[(size_t)e0.x * F4 + c];
        acc.x = fmaf(w0, v0.x, acc.x); acc.y = fmaf(w0, v0.y, acc.y);
        acc.z = fmaf(w0, v0.z, acc.z); acc.w = fmaf(w0, v0.w, acc.w);
    }
    float4 bb = b24[c];
    float r0 = fmaxf(acc.x + bb.x, 0.f);
    float r1 = fmaxf(acc.y + bb.y, 0.f);
    float r2 = fmaxf(acc.z + bb.z, 0.f);
    float r3 = fmaxf(acc.w + bb.w, 0.f);
    float* gp = &G[(size_t)seg[d] * HID + c * 4];
    atomicAdd(gp + 0, r0);
    atomicAdd(gp + 1, r1);
    atomicAdd(gp + 2, r2);
    atomicAdd(gp + 3, r3);
}

// ---------------------------------------------------------------------------
// 5/6. 2-term GEMM with pre-converted bf16 A and pre-split bf16 B hi/lo.
//      Staging = pure copies. D = A*Bhi + A*Blo. Double-buffered.
//      BM=128 BN=128 BK=32, 8 warps, 64x32 warp tile, mma.m16n8k16.bf16
// ---------------------------------------------------------------------------
__device__ __forceinline__ void ldsm_x4(uint32_t& r0, uint32_t& r1,
                                        uint32_t& r2, uint32_t& r3, uint32_t a) {
    asm volatile("ldmatrix.sync.aligned.m8n8.x4.shared.b16 {%0,%1,%2,%3},[%4];"
                 : "=r"(r0), "=r"(r1), "=r"(r2), "=r"(r3) : "r"(a));
}
__device__ __forceinline__ void ldsm_x2t(uint32_t& r0, uint32_t& r1, uint32_t a) {
    asm volatile("ldmatrix.sync.aligned.m8n8.x2.trans.shared.b16 {%0,%1},[%2];"
                 : "=r"(r0), "=r"(r1) : "r"(a));
}
__device__ __forceinline__ void mma16(float* c, const uint32_t* a, const uint32_t* b) {
    asm volatile(
        "mma.sync.aligned.m16n8k16.row.col.f32.bf16.bf16.f32 "
        "{%0,%1,%2,%3},{%4,%5,%6,%7},{%8,%9},{%0,%1,%2,%3};"
        : "+f"(c[0]), "+f"(c[1]), "+f"(c[2]), "+f"(c[3])
        : "r"(a[0]), "r"(a[1]), "r"(a[2]), "r"(a[3]), "r"(b[0]), "r"(b[1]));
}

// smem layout (bf16 element offsets)
#define GBM 128
#define GBN 128
#define GBK 32
#define GAKS 40                         // A row stride (bf16)
#define GBKS 136                        // B row stride (bf16)
#define A_ELE (GBM * GAKS)              // 5120 per buffer
#define B_ELE (GBK * GBKS)              // 4352 per buffer
#define OFF_A   0                       // 2 buffers: 10240
#define OFF_BHI (2 * A_ELE)             // 10240 (+2*B_ELE)
#define OFF_BLO (2 * A_ELE + 2 * B_ELE) // 18944
#define GEMM_SMEM_BYTES ((2 * A_ELE + 4 * B_ELE) * 2)  // 55296 B

template <int FUSE_BIAS_RELU, int OUT_BF16>
__global__ __launch_bounds__(256, 1)
void bf16w_gemm_kernel(const __nv_bfloat16* __restrict__ A,
                       const __nv_bfloat16* __restrict__ Bhi,
                       const __nv_bfloat16* __restrict__ Blo,
                       const float* __restrict__ bias,
                       float* __restrict__ Cf, __nv_bfloat16* __restrict__ Cb,
                       int M, int N, int K) {
    extern __shared__ __nv_bfloat16 sm[];

    const int tid  = threadIdx.x;
    const int lane = tid & 31;
    const int warp = tid >> 5;
    const int wm = warp >> 2;          // 0..1  (64-row slab)
    const int wn = warp & 3;           // 0..3  (32-col slab)
    const int gr = lane >> 2;          // 0..7
    const int gc = lane & 3;           // 0..3
    const int bm = blockIdx.x * GBM;
    const int bn = blockIdx.y * GBN;

    const uint32_t base = (uint32_t)__cvta_generic_to_shared(sm);

    const int a_row_l = wm * 64 + ((lane >> 3) & 1) * 8 + (lane & 7); // + mi*16
    const int a_k_l   = (lane >> 4) * 8;                              // + ks*16
    const int b_k_l   = (lane & 7) + ((lane >> 3) & 1) * 8;           // + ks*16

    float acc[4][4][4];
    #pragma unroll
    for (int mi = 0; mi < 4; mi++)
        #pragma unroll
        for (int ni = 0; ni < 4; ni++)
            #pragma unroll
            for (int r = 0; r < 4; r++) acc[mi][ni][r] = 0.0f;

    const int nTiles = K / GBK;

    // loader addressing: A tile 128x32 bf16 = 512 uint4 (2/thread);
    //                    B tiles (hi+lo) 32x128 bf16 = 512 uint4 each (2/thread each)
    const int arow[2] = { tid >> 2, (tid + 256) >> 2 };   // 0..127
    const int acq  = (tid & 3) * 8;                       // 0,8,16,24
    const int brow[2] = { tid >> 4, (tid + 256) >> 4 };   // 0..31
    const int bcq  = (tid & 15) * 8;                      // 0..120

    uint4 aR[2], bhiR[2], bloR[2];

    auto loadRegs = [&](int kt) {
        int k0 = kt * GBK;
        #pragma unroll
        for (int i = 0; i < 2; i++) {
            aR[i] = (bm + arow[i] < M)
                      ? *(const uint4*)(A + (size_t)(bm + arow[i]) * K + k0 + acq)
                      : make_uint4(0, 0, 0, 0);
            bhiR[i] = *(const uint4*)(Bhi + (size_t)(k0 + brow[i]) * N + bn + bcq);
            bloR[i] = *(const uint4*)(Blo + (size_t)(k0 + brow[i]) * N + bn + bcq);
        }
    };
    auto storeBuf = [&](int buf) {
        #pragma unroll
        for (int i = 0; i < 2; i++) {
            *(uint4*)(sm + OFF_A   + buf * A_ELE + arow[i] * GAKS + acq) = aR[i];
            *(uint4*)(sm + OFF_BHI + buf * B_ELE + brow[i] * GBKS + bcq) = bhiR[i];
            *(uint4*)(sm + OFF_BLO + buf * B_ELE + brow[i] * GBKS + bcq) = bloR[i];
        }
    };

    loadRegs(0);
    storeBuf(0);
    __syncthreads();

    for (int kt = 0; kt < nTiles; kt++) {
        const int buf = kt & 1;
        const uint32_t aOff = base + (uint32_t)((OFF_A   + buf * A_ELE) * 2);
        const uint32_t bHi  = base + (uint32_t)((OFF_BHI + buf * B_ELE) * 2);
        const uint32_t bLo  = base + (uint32_t)((OFF_BLO + buf * B_ELE) * 2);

        if (kt + 1 < nTiles) loadRegs(kt + 1);

        #pragma unroll
        for (int ks = 0; ks < 2; ks++) {
            uint32_t ahi[4][4], bhi[4][2], blo[4][2];
            #pragma unroll
            for (int mi = 0; mi < 4; mi++) {
                uint32_t off = (uint32_t)(((a_row_l + mi * 16) * GAKS +
                                           ks * 16 + a_k_l) * 2);
                ldsm_x4(ahi[mi][0], ahi[mi][1], ahi[mi][2], ahi[mi][3], aOff + off);
            }
            #pragma unroll
            for (int ni = 0; ni < 4; ni++) {
                uint32_t off = (uint32_t)(((ks * 16 + b_k_l) * GBKS +
                                           wn * 32 + ni * 8) * 2);
                ldsm_x2t(bhi[ni][0], bhi[ni][1], bHi + off);
                ldsm_x2t(blo[ni][0], blo[ni][1], bLo + off);
            }
            #pragma unroll
            for (int mi = 0; mi < 4; mi++)
                #pragma unroll
                for (int ni = 0; ni < 4; ni++) {
                    mma16(acc[mi][ni], ahi[mi], bhi[ni]);
                    mma16(acc[mi][ni], ahi[mi], blo[ni]);
                }
        }

        if (kt + 1 < nTiles) {
            storeBuf((kt + 1) & 1);   // other buffer: no hazard with current reads
            __syncthreads();
        }
    }

    // epilogue (D layout: c0=(gr,2gc) c1=(gr,2gc+1) c2=(gr+8,2gc) c3=(gr+8,2gc+1))
    #pragma unroll
    for (int mi = 0; mi < 4; mi++) {
        int row0 = bm + wm * 64 + mi * 16 + gr;
        int row1 = row0 + 8;
        #pragma unroll
        for (int ni = 0; ni < 4; ni++) {
            int col = bn + wn * 32 + ni * 8 + gc * 2;
            float v0 = acc[mi][ni][0], v1 = acc[mi][ni][1];
            float v2 = acc[mi][ni][2], v3 = acc[mi][ni][3];
            if (FUSE_BIAS_RELU) {
                float bb0 = bias[col], bb1 = bias[col + 1];
                v0 = fmaxf(v0 + bb0, 0.f); v1 = fmaxf(v1 + bb1, 0.f);
                v2 = fmaxf(v2 + bb0, 0.f); v3 = fmaxf(v3 + bb1, 0.f);
            }
            if (OUT_BF16) {
                if (row0 < M) *(uint32_t*)&Cb[(size_t)row0 * N + col] = cvt2(v0, v1);
                if (row1 < M) *(uint32_t*)&Cb[(size_t)row1 * N + col] = cvt2(v2, v3);
            } else {
                if (row0 < M) { float2 s = {v0, v1}; *(float2*)&Cf[(size_t)row0 * N + col] = s; }
                if (row1 < M) { float2 s = {v2, v3}; *(float2*)&Cf[(size_t)row1 * N + col] = s; }
            }
        }
    }
}

// ---------------------------------------------------------------------------
// 8. dense head: out[b] = relu(G[b]@Wd + bd) @ Wo + bo
// ---------------------------------------------------------------------------
__global__ void head_kernel(const float* __restrict__ G, const float* __restrict__ Wd,
                            const float* __restrict__ bd, const float* __restrict__ Wo,
                            const float* __restrict__ bo, float* __restrict__ out) {
    __shared__ float gs[HID];
    __shared__ float red[HID];
    const int b = blockIdx.x, t = threadIdx.x;
    gs[t] = G[(size_t)b * HID + t];
    __syncthreads();
    float acc = bd[t];
    #pragma unroll 4
    for (int k = 0; k < HID; k++) acc = fmaf(gs[k], Wd[(size_t)k * HID + t], acc);
    acc = fmaxf(acc, 0.0f) * Wo[t];
    red[t] = acc;
    __syncthreads();
    for (int s = HID / 2; s > 0; s >>= 1) {
        if (t < s) red[t] += red[t + s];
        __syncthreads();
    }
    if (t == 0) out[b] = red[0] + bo[0];
}

// ---------------------------------------------------------------------------
// launch
// ---------------------------------------------------------------------------
extern "C" void kernel_launch(void* const* d_in, const int* in_sizes, int n_in,
                              void* d_out, int out_size) {
    const float* x        = (const float*)d_in[0];   // [N,128]
    const int*   edge_src = (const int*)  d_in[1];   // [E]
    const int*   edge_dst = (const int*)  d_in[2];   // [E]
    const float* edge_w   = (const float*)d_in[3];   // [E]
    const int*   seg_ids  = (const int*)  d_in[4];   // [N]
    const float* W1 = (const float*)d_in[5];         // [128,256]
    const float* b1 = (const float*)d_in[6];
    const float* W2 = (const float*)d_in[7];         // [256,256]
    const float* b2 = (const float*)d_in[8];
    const float* Wd = (const float*)d_in[9];         // [256,256]
    const float* bd = (const float*)d_in[10];
    const float* Wo = (const float*)d_in[11];        // [256,1]
    const float* bo = (const float*)d_in[12];
    float* out = (float*)d_out;                      // [128]

    float *pT2, *pG;
    __nv_bfloat16 *pAX, *pH1, *pW1hi, *pW1lo, *pW2hi, *pW2lo;
    int *pdeg, *prptr, *pcursor, *pbsum;
    int2 *pedge;
    cudaGetSymbolAddress((void**)&pAX, d_AX);
    cudaGetSymbolAddress((void**)&pH1, d_H1);
    cudaGetSymbolAddress((void**)&pT2, d_T2);
    cudaGetSymbolAddress((void**)&pW1hi, d_W1hi);
    cudaGetSymbolAddress((void**)&pW1lo, d_W1lo);
    cudaGetSymbolAddress((void**)&pW2hi, d_W2hi);
    cudaGetSymbolAddress((void**)&pW2lo, d_W2lo);
    cudaGetSymbolAddress((void**)&pG, d_G);
    cudaGetSymbolAddress((void**)&pdeg, d_deg);
    cudaGetSymbolAddress((void**)&prptr, d_rptr);
    cudaGetSymbolAddress((void**)&pcursor, d_cursor);
    cudaGetSymbolAddress((void**)&pedge, d_edge);
    cudaGetSymbolAddress((void**)&pbsum, d_bsum);

    cudaFuncSetAttribute(bf16w_gemm_kernel<1, 1>,
                         cudaFuncAttributeMaxDynamicSharedMemorySize, GEMM_SMEM_BYTES);
    cudaFuncSetAttribute(bf16w_gemm_kernel<0, 0>,
                         cudaFuncAttributeMaxDynamicSharedMemorySize, GEMM_SMEM_BYTES);

    // 0. zero deg + pooled accumulator; split weights into bf16 hi/lo planes
    zero_kernel<<<(NNODES + 255) / 256, 256>>>(pdeg, pG);
    split_w_kernel<<<((FIN * HID + HID * HID) / 2 + 255) / 256, 256>>>(
        W1, W2, pW1hi, pW1lo, pW2hi, pW2lo);
    // 1-3. build CSR-by-dst (parallel 3-phase scan)
    hist_kernel<<<(NEDGES + 255) / 256, 256>>>(edge_dst, pdeg);
    scan_blocks<<<NSCANB, 256>>>(pdeg, prptr, pbsum);
    scan_bsums<<<1, 256>>>(pbsum, prptr);
    add_offs<<<NSCANB, 256>>>(prptr, pbsum, pcursor);
    fill_kernel<<<(NEDGES + 255) / 256, 256>>>(edge_src, edge_dst, edge_w,
                                               pcursor, pedge);
    // 4. AX = A @ X (fp32 gathers, bf16 output — exactly GEMM1's A rounding)
    spmm_csr_bf16out<<<(NNODES + 7) / 8, 256>>>(
        (const float4*)x, prptr, pedge, (uint2*)pAX);
    // 5. H1 = relu(AX @ W1 + b1)   [bf16 A, pre-split B; bf16 out]
    {
        dim3 grid((NNODES + 127) / 128, HID / 128);
        bf16w_gemm_kernel<1, 1><<<grid, 256, GEMM_SMEM_BYTES>>>(
            pAX, pW1hi, pW1lo, b1, nullptr, pH1, NNODES, HID, FIN);
    }
    // 6. T2 = H1 @ W2              [bf16 A, pre-split B; fp32 out]
    {
        dim3 grid((NNODES + 127) / 128, HID / 128);
        bf16w_gemm_kernel<0, 0><<<grid, 256, GEMM_SMEM_BYTES>>>(
            pH1, pW2hi, pW2lo, nullptr, pT2, nullptr, NNODES, HID, HID);
    }
    // 7. G[seg] += relu(spmm(T2) + b2)
    {
        constexpr int NPB = 256 / (HID / 4);   // 4 nodes / block
        spmm_pool_v4<<<(NNODES + NPB - 1) / NPB, 256>>>(
            (const float4*)pT2, prptr, pedge, (const float4*)b2, seg_ids, pG);
    }
    // 8. head
    head_kernel<<<NGRAPH, HID>>>(pG, Wd, bd, Wo, bo, out);
}

// round 16
// speedup vs baseline: 1.0961x; 1.0961x over previous
#include <cuda_runtime.h>
#include <cuda_bf16.h>
#include <cstdint>

// Problem constants
#define NNODES 50000
#define NEDGES 800000
#define FIN    128
#define HID    256
#define NGRAPH 128
#define NSCANB ((NNODES + 255) / 256)   // 196 scan blocks

// ---------------------------------------------------------------------------
// Scratch (static __device__ arrays; no allocation allowed)
// ---------------------------------------------------------------------------
__device__ float d_AX[(size_t)NNODES * FIN];           // A @ X            [N,128]
__device__ float d_H1[(size_t)NNODES * HID];           // relu(AX@W1+b1)   [N,256]
__device__ __nv_bfloat16 d_T2[(size_t)NNODES * HID];   // H1 @ W2 (bf16)   [N,256]
__device__ int   d_deg[NNODES];
__device__ int   d_rptr[NNODES + 1];
__device__ int   d_cursor[NNODES];
__device__ int   d_bsum[256];
__device__ int   d_csrc[NEDGES];
__device__ float d_csrw[NEDGES];
__device__ float d_G[NGRAPH * HID];                    // pooled graph features

// ---------------------------------------------------------------------------
// 0. zero deg + G
// ---------------------------------------------------------------------------
__global__ void zero_kernel(int* deg, float* G) {
    int i = blockIdx.x * blockDim.x + threadIdx.x;
    if (i < NNODES) deg[i] = 0;
    if (i < NGRAPH * HID) G[i] = 0.0f;
}

// ---------------------------------------------------------------------------
// 1. degree histogram over edge_dst
// ---------------------------------------------------------------------------
__global__ void hist_kernel(const int* __restrict__ dst, int* __restrict__ deg) {
    int e = blockIdx.x * blockDim.x + threadIdx.x;
    if (e < NEDGES) atomicAdd(&deg[dst[e]], 1);
}

// ---------------------------------------------------------------------------
// 2a. per-block exclusive prescan: pre[i] (in rptr), block totals in bsum
// ---------------------------------------------------------------------------
__global__ __launch_bounds__(256)
void scan_blocks(const int* __restrict__ deg, int* __restrict__ pre,
                 int* __restrict__ bsum) {
    __shared__ int ws[8];
    const int t = threadIdx.x, lane = t & 31, wid = t >> 5;
    const int i = blockIdx.x * 256 + t;
    int v = (i < NNODES) ? deg[i] : 0;
    int x = v;
    #pragma unroll
    for (int off = 1; off < 32; off <<= 1) {
        int y = __shfl_up_sync(0xffffffffu, x, off);
        if (lane >= off) x += y;
    }
    if (lane == 31) ws[wid] = x;
    __syncthreads();
    if (wid == 0) {
        int s = (lane < 8) ? ws[lane] : 0;
        #pragma unroll
        for (int off = 1; off < 8; off <<= 1) {
            int y = __shfl_up_sync(0xffffffffu, s, off);
            if (lane >= off) s += y;
        }
        if (lane < 8) ws[lane] = s;     // inclusive warp sums
    }
    __syncthreads();
    int incl = x + (wid > 0 ? ws[wid - 1] : 0);
    if (i < NNODES) pre[i] = incl - v;  // block-local exclusive
    if (t == 255) bsum[blockIdx.x] = incl;
}

// ---------------------------------------------------------------------------
// 2b. scan the 196 block totals (one block); writes rptr[NNODES]
// ---------------------------------------------------------------------------
__global__ __launch_bounds__(256)
void scan_bsums(int* __restrict__ bsum, int* __restrict__ rptr) {
    __shared__ int ws[8];
    const int t = threadIdx.x, lane = t & 31, wid = t >> 5;
    int v = (t < NSCANB) ? bsum[t] : 0;
    int x = v;
    #pragma unroll
    for (int off = 1; off < 32; off <<= 1) {
        int y = __shfl_up_sync(0xffffffffu, x, off);
        if (lane >= off) x += y;
    }
    if (lane == 31) ws[wid] = x;
    __syncthreads();
    if (wid == 0) {
        int s = (lane < 8) ? ws[lane] : 0;
        #pragma unroll
        for (int off = 1; off < 8; off <<= 1) {
            int y = __shfl_up_sync(0xffffffffu, s, off);
            if (lane >= off) s += y;
        }
        if (lane < 8) ws[lane] = s;
    }
    __syncthreads();
    int incl = x + (wid > 0 ? ws[wid - 1] : 0);
    bsum[t] = incl - v;                 // exclusive block offsets
    if (t == NSCANB - 1) rptr[NNODES] = incl;
}

// ---------------------------------------------------------------------------
// 2c. add block offsets in place; seed cursor
// ---------------------------------------------------------------------------
__global__ __launch_bounds__(256)
void add_offs(int* __restrict__ rptr, const int* __restrict__ bsum,
              int* __restrict__ cursor) {
    const int i = blockIdx.x * 256 + threadIdx.x;
    if (i < NNODES) {
        int r = rptr[i] + bsum[blockIdx.x];
        rptr[i] = r;
        cursor[i] = r;
    }
}

// ---------------------------------------------------------------------------
// 3. scatter edges into CSR slots
// ---------------------------------------------------------------------------
__global__ void fill_kernel(const int* __restrict__ src, const int* __restrict__ dst,
                            const float* __restrict__ w, int* __restrict__ cursor,
                            int* __restrict__ csrc, float* __restrict__ csrw) {
    int e = blockIdx.x * blockDim.x + threadIdx.x;
    if (e < NEDGES) {
        int d   = dst[e];
        int pos = atomicAdd(&cursor[d], 1);
        csrc[pos] = src[e];
        csrw[pos] = w[e];
    }
}

// ---------------------------------------------------------------------------
// 4. CSR gather spmm, float4 columns: Y[d,:] = sum_e w_e * X[src_e,:]
// ---------------------------------------------------------------------------
template <int F4>
__global__ __launch_bounds__(256)
void spmm_csr_v4(const float4* __restrict__ X4,
                 const int* __restrict__ rptr,
                 const int* __restrict__ cs,
                 const float* __restrict__ cw,
                 float4* __restrict__ Y4) {
    constexpr int NPB = 256 / F4;
    const int g = threadIdx.x / F4;
    const int c = threadIdx.x % F4;
    const int d = blockIdx.x * NPB + g;
    if (d >= NNODES) return;
    const int b = rptr[d], e = rptr[d + 1];
    float4 acc = make_float4(0.f, 0.f, 0.f, 0.f);
    int i = b;
    for (; i + 4 <= e; i += 4) {
        int   s0 = cs[i], s1 = cs[i + 1], s2 = cs[i + 2], s3 = cs[i + 3];
        float w0 = cw[i], w1 = cw[i + 1], w2 = cw[i + 2], w3 = cw[i + 3];
        float4 v0 = X4[(size_t)s0 * F4 + c];
        float4 v1 = X4[(size_t)s1 * F4 + c];
        float4 v2 = X4[(size_t)s2 * F4 + c];
        float4 v3 = X4[(size_t)s3 * F4 + c];
        acc.x = fmaf(w0, v0.x, acc.x); acc.y = fmaf(w0, v0.y, acc.y);
        acc.z = fmaf(w0, v0.z, acc.z); acc.w = fmaf(w0, v0.w, acc.w);
        acc.x = fmaf(w1, v1.x, acc.x); acc.y = fmaf(w1, v1.y, acc.y);
        acc.z = fmaf(w1, v1.z, acc.z); acc.w = fmaf(w1, v1.w, acc.w);
        acc.x = fmaf(w2, v2.x, acc.x); acc.y = fmaf(w2, v2.y, acc.y);
        acc.z = fmaf(w2, v2.z, acc.z); acc.w = fmaf(w2, v2.w, acc.w);
        acc.x = fmaf(w3, v3.x, acc.x); acc.y = fmaf(w3, v3.y, acc.y);
        acc.z = fmaf(w3, v3.z, acc.z); acc.w = fmaf(w3, v3.w, acc.w);
    }
    for (; i < e; i++) {
        float w0 = cw[i];
        float4 v0 = X4[(size_t)cs[i] * F4 + c];
        acc.x = fmaf(w0, v0.x, acc.x); acc.y = fmaf(w0, v0.y, acc.y);
        acc.z = fmaf(w0, v0.z, acc.z); acc.w = fmaf(w0, v0.w, acc.w);
    }
    Y4[(size_t)d * F4 + c] = acc;
}

// ---------------------------------------------------------------------------
// 7. spmm2 pool over bf16 T2 — SAME geometry as the fp32 version
//    (64 threads/node, NPB=4, 4-edge unroll), but uint2 (4 bf16) loads.
//    ALU-only unpack (SHF/LOP), fp32 accumulate, bias+relu+atomic pool.
// ---------------------------------------------------------------------------
__global__ __launch_bounds__(256)
void spmm_pool_bf16(const uint2* __restrict__ Tb,
                    const int* __restrict__ rptr,
                    const int* __restrict__ cs,
                    const float* __restrict__ cw,
                    const float4* __restrict__ b24,
                    const int* __restrict__ seg,
                    float* __restrict__ G) {
    constexpr int F = HID / 4;            // 64 threads per node (same as R14)
    constexpr int NPB = 256 / F;          // 4 nodes / block, grid 12500
    const int g = threadIdx.x / F;
    const int c = threadIdx.x % F;        // handles bf16 cols 4c..4c+3
    const int d = blockIdx.x * NPB + g;
    if (d >= NNODES) return;
    const int b = rptr[d], e = rptr[d + 1];
    float a0 = 0.f, a1 = 0.f, a2 = 0.f, a3 = 0.f;
    int i = b;
    #define POOL_FMA(v, w)                                            \
        {                                                             \
            a0 = fmaf(w, __uint_as_float((v).x << 16), a0);           \
            a1 = fmaf(w, __uint_as_float((v).x & 0xffff0000u), a1);   \
            a2 = fmaf(w, __uint_as_float((v).y << 16), a2);           \
            a3 = fmaf(w, __uint_as_float((v).y & 0xffff0000u), a3);   \
        }
    for (; i + 4 <= e; i += 4) {
        int   s0 = cs[i], s1 = cs[i + 1], s2 = cs[i + 2], s3 = cs[i + 3];
        float w0 = cw[i], w1 = cw[i + 1], w2 = cw[i + 2], w3 = cw[i + 3];
        uint2 v0 = Tb[(size_t)s0 * F + c];
        uint2 v1 = Tb[(size_t)s1 * F + c];
        uint2 v2 = Tb[(size_t)s2 * F + c];
        uint2 v3 = Tb[(size_t)s3 * F + c];
        POOL_FMA(v0, w0);
        POOL_FMA(v1, w1);
        POOL_FMA(v2, w2);
        POOL_FMA(v3, w3);
    }
    for (; i < e; i++) {
        uint2 v0 = Tb[(size_t)cs[i] * F + c];
        float w0 = cw[i];
        POOL_FMA(v0, w0);
    }
    #undef POOL_FMA
    float4 bb = b24[c];
    float r0 = fmaxf(a0 + bb.x, 0.f);
    float r1 = fmaxf(a1 + bb.y, 0.f);
    float r2 = fmaxf(a2 + bb.z, 0.f);
    float r3 = fmaxf(a3 + bb.w, 0.f);
    float* gp = &G[(size_t)seg[d] * HID + c * 4];
    atomicAdd(gp + 0, r0);
    atomicAdd(gp + 1, r1);
    atomicAdd(gp + 2, r2);
    atomicAdd(gp + 3, r3);
}

// ---------------------------------------------------------------------------
// 5/6. 2-term bf16-split tensor-core GEMM (A-hi only, B hi+lo),
//      double-buffered smem pipeline. OUT_BF16 selects bf16 output.
//      BM=128 BN=128 BK=32, 8 warps, 64x32 warp tile, mma.m16n8k16.bf16
// ---------------------------------------------------------------------------
__device__ __forceinline__ void ldsm_x4(uint32_t& r0, uint32_t& r1,
                                        uint32_t& r2, uint32_t& r3, uint32_t a) {
    asm volatile("ldmatrix.sync.aligned.m8n8.x4.shared.b16 {%0,%1,%2,%3},[%4];"
                 : "=r"(r0), "=r"(r1), "=r"(r2), "=r"(r3) : "r"(a));
}
__device__ __forceinline__ void ldsm_x2t(uint32_t& r0, uint32_t& r1, uint32_t a) {
    asm volatile("ldmatrix.sync.aligned.m8n8.x2.trans.shared.b16 {%0,%1},[%2];"
                 : "=r"(r0), "=r"(r1) : "r"(a));
}
__device__ __forceinline__ void mma16(float* c, const uint32_t* a, const uint32_t* b) {
    asm volatile(
        "mma.sync.aligned.m16n8k16.row.col.f32.bf16.bf16.f32 "
        "{%0,%1,%2,%3},{%4,%5,%6,%7},{%8,%9},{%0,%1,%2,%3};"
        : "+f"(c[0]), "+f"(c[1]), "+f"(c[2]), "+f"(c[3])
        : "r"(a[0]), "r"(a[1]), "r"(a[2]), "r"(a[3]), "r"(b[0]), "r"(b[1]));
}
__device__ __forceinline__ uint32_t cvt2(float x, float y) {
    uint32_t h;
    asm("cvt.rn.bf16x2.f32 %0, %1, %2;" : "=r"(h) : "f"(y), "f"(x));  // lo16=x
    return h;
}
__device__ __forceinline__ void split2(float x, float y, uint32_t& hi, uint32_t& lo) {
    uint32_t h = cvt2(x, y);
    float hx = __uint_as_float(h << 16);
    float hy = __uint_as_float(h & 0xffff0000u);
    lo = cvt2(x - hx, y - hy);
    hi = h;
}

// smem layout (bf16 element offsets)
#define GBM 128
#define GBN 128
#define GBK 32
#define GAKS 40                         // A row stride
#define GBKS 136                        // B row stride
#define A_ELE (GBM * GAKS)              // 5120 per buffer
#define B_ELE (GBK * GBKS)              // 4352 per buffer
#define OFF_AHI 0
#define OFF_BHI (2 * A_ELE)             // 10240
#define OFF_BLO (2 * A_ELE + 2 * B_ELE) // 18944
#define GEMM_SMEM_BYTES ((2 * A_ELE + 4 * B_ELE) * 2)  // 55296 B

template <int FUSE_BIAS_RELU, int OUT_BF16>
__global__ __launch_bounds__(256, 1)
void bf16x2_gemm_kernel(const float* __restrict__ A, const float* __restrict__ B,
                        const float* __restrict__ bias, float* __restrict__ Cf,
                        __nv_bfloat16* __restrict__ Cb,
                        int M, int N, int K) {
    extern __shared__ __nv_bfloat16 sm[];

    const int tid  = threadIdx.x;
    const int lane = tid & 31;
    const int warp = tid >> 5;
    const int wm = warp >> 2;          // 0..1  (64-row slab)
    const int wn = warp & 3;           // 0..3  (32-col slab)
    const int gr = lane >> 2;          // 0..7
    const int gc = lane & 3;           // 0..3
    const int bm = blockIdx.x * GBM;
    const int bn = blockIdx.y * GBN;

    const uint32_t base = (uint32_t)__cvta_generic_to_shared(sm);

    const int a_row_l = wm * 64 + ((lane >> 3) & 1) * 8 + (lane & 7); // + mi*16
    const int a_k_l   = (lane >> 4) * 8;                              // + ks*16
    const int b_k_l   = (lane & 7) + ((lane >> 3) & 1) * 8;           // + ks*16

    float acc[4][4][4];
    #pragma unroll
    for (int mi = 0; mi < 4; mi++)
        #pragma unroll
        for (int ni = 0; ni < 4; ni++)
            #pragma unroll
            for (int r = 0; r < 4; r++) acc[mi][ni][r] = 0.0f;

    const int nTiles = K / GBK;

    const int arow[4] = { (tid) >> 3, (tid + 256) >> 3, (tid + 512) >> 3, (tid + 768) >> 3 };
    const int akq  = (tid & 7) * 4;
    const int brow[4] = { tid >> 5, (tid + 256) >> 5, (tid + 512) >> 5, (tid + 768) >> 5 };
    const int bcol = (tid & 31) * 4;

    float4 aReg[4], bReg[4];

    auto loadRegs = [&](int kt) {
        int k0 = kt * GBK;
        #pragma unroll
        for (int i = 0; i < 4; i++) {
            aReg[i] = (bm + arow[i] < M)
                        ? *(const float4*)(A + (size_t)(bm + arow[i]) * K + k0 + akq)
                        : make_float4(0.f, 0.f, 0.f, 0.f);
            bReg[i] = *(const float4*)(B + (size_t)(k0 + brow[i]) * N + bn + bcol);
        }
    };
    auto storeBuf = [&](int buf) {
        #pragma unroll
        for (int i = 0; i < 4; i++) {
            int ao = buf * A_ELE + arow[i] * GAKS + akq;
            uint32_t h0 = cvt2(aReg[i].x, aReg[i].y);
            uint32_t h1 = cvt2(aReg[i].z, aReg[i].w);
            *(uint2*)(sm + OFF_AHI + ao) = make_uint2(h0, h1);
            int bo = buf * B_ELE + brow[i] * GBKS + bcol;
            uint32_t l0, l1;
            split2(bReg[i].x, bReg[i].y, h0, l0);
            split2(bReg[i].z, bReg[i].w, h1, l1);
            *(uint2*)(sm + OFF_BHI + bo) = make_uint2(h0, h1);
            *(uint2*)(sm + OFF_BLO + bo) = make_uint2(l0, l1);
        }
    };

    loadRegs(0);
    storeBuf(0);
    __syncthreads();

    for (int kt = 0; kt < nTiles; kt++) {
        const int buf = kt & 1;
        const uint32_t aOff = base + (uint32_t)((OFF_AHI + buf * A_ELE) * 2);
        const uint32_t bHi  = base + (uint32_t)((OFF_BHI + buf * B_ELE) * 2);
        const uint32_t bLo  = base + (uint32_t)((OFF_BLO + buf * B_ELE) * 2);

        if (kt + 1 < nTiles) loadRegs(kt + 1);

        #pragma unroll
        for (int ks = 0; ks < 2; ks++) {
            uint32_t ahi[4][4], bhi[4][2], blo[4][2];
            #pragma unroll
            for (int mi = 0; mi < 4; mi++) {
                uint32_t off = (uint32_t)(((a_row_l + mi * 16) * GAKS +
                                           ks * 16 + a_k_l) * 2);
                ldsm_x4(ahi[mi][0], ahi[mi][1], ahi[mi][2], ahi[mi][3], aOff + off);
            }
            #pragma unroll
            for (int ni = 0; ni < 4; ni++) {
                uint32_t off = (uint32_t)(((ks * 16 + b_k_l) * GBKS +
                                           wn * 32 + ni * 8) * 2);
                ldsm_x2t(bhi[ni][0], bhi[ni][1], bHi + off);
                ldsm_x2t(blo[ni][0], blo[ni][1], bLo + off);
            }
            #pragma unroll
            for (int mi = 0; mi < 4; mi++)
                #pragma unroll
                for (int ni = 0; ni < 4; ni++) {
                    mma16(acc[mi][ni], ahi[mi], bhi[ni]);
                    mma16(acc[mi][ni], ahi[mi], blo[ni]);
                }
        }

        if (kt + 1 < nTiles) {
            storeBuf((kt + 1) & 1);   // other buffer: no hazard with current reads
            __syncthreads();
        }
    }

    // epilogue (D layout: c0=(gr,2gc) c1=(gr,2gc+1) c2=(gr+8,2gc) c3=(gr+8,2gc+1))
    #pragma unroll
    for (int mi = 0; mi < 4; mi++) {
        int row0 = bm + wm * 64 + mi * 16 + gr;
        int row1 = row0 + 8;
        #pragma unroll
        for (int ni = 0; ni < 4; ni++) {
            int col = bn + wn * 32 + ni * 8 + gc * 2;
            float v0 = acc[mi][ni][0], v1 = acc[mi][ni][1];
            float v2 = acc[mi][ni][2], v3 = acc[mi][ni][3];
            if (FUSE_BIAS_RELU) {
                float bb0 = bias[col], bb1 = bias[col + 1];
                v0 = fmaxf(v0 + bb0, 0.f); v1 = fmaxf(v1 + bb1, 0.f);
                v2 = fmaxf(v2 + bb0, 0.f); v3 = fmaxf(v3 + bb1, 0.f);
            }
            if (OUT_BF16) {
                if (row0 < M) *(uint32_t*)&Cb[(size_t)row0 * N + col] = cvt2(v0, v1);
                if (row1 < M) *(uint32_t*)&Cb[(size_t)row1 * N + col] = cvt2(v2, v3);
            } else {
                if (row0 < M) { float2 s = {v0, v1}; *(float2*)&Cf[(size_t)row0 * N + col] = s; }
                if (row1 < M) { float2 s = {v2, v3}; *(float2*)&Cf[(size_t)row1 * N + col] = s; }
            }
        }
    }
}

// ---------------------------------------------------------------------------
// 8. dense head: out[b] = relu(G[b]@Wd + bd) @ Wo + bo
// ---------------------------------------------------------------------------
__global__ void head_kernel(const float* __restrict__ G, const float* __restrict__ Wd,
                            const float* __restrict__ bd, const float* __restrict__ Wo,
                            const float* __restrict__ bo, float* __restrict__ out) {
    __shared__ float gs[HID];
    __shared__ float red[HID];
    const int b = blockIdx.x, t = threadIdx.x;
    gs[t] = G[(size_t)b * HID + t];
    __syncthreads();
    float acc = bd[t];
    #pragma unroll 4
    for (int k = 0; k < HID; k++) acc = fmaf(gs[k], Wd[(size_t)k * HID + t], acc);
    acc = fmaxf(acc, 0.0f) * Wo[t];
    red[t] = acc;
    __syncthreads();
    for (int s = HID / 2; s > 0; s >>= 1) {
        if (t < s) red[t] += red[t + s];
        __syncthreads();
    }
    if (t == 0) out[b] = red[0] + bo[0];
}

// ---------------------------------------------------------------------------
// launch
// ---------------------------------------------------------------------------
extern "C" void kernel_launch(void* const* d_in, const int* in_sizes, int n_in,
                              void* d_out, int out_size) {
    const float* x        = (const float*)d_in[0];   // [N,128]
    const int*   edge_src = (const int*)  d_in[1];   // [E]
    const int*   edge_dst = (const int*)  d_in[2];   // [E]
    const float* edge_w   = (const float*)d_in[3];   // [E]
    const int*   seg_ids  = (const int*)  d_in[4];   // [N]
    const float* W1 = (const float*)d_in[5];         // [128,256]
    const float* b1 = (const float*)d_in[6];
    const float* W2 = (const float*)d_in[7];         // [256,256]
    const float* b2 = (const float*)d_in[8];
    const float* Wd = (const float*)d_in[9];         // [256,256]
    const float* bd = (const float*)d_in[10];
    const float* Wo = (const float*)d_in[11];        // [256,1]
    const float* bo = (const float*)d_in[12];
    float* out = (float*)d_out;                      // [128]

    float *pAX, *pH1, *pG, *pcsrw;
    __nv_bfloat16 *pT2;
    int *pdeg, *prptr, *pcursor, *pcsrc, *pbsum;
    cudaGetSymbolAddress((void**)&pAX, d_AX);
    cudaGetSymbolAddress((void**)&pH1, d_H1);
    cudaGetSymbolAddress((void**)&pT2, d_T2);
    cudaGetSymbolAddress((void**)&pG, d_G);
    cudaGetSymbolAddress((void**)&pdeg, d_deg);
    cudaGetSymbolAddress((void**)&prptr, d_rptr);
    cudaGetSymbolAddress((void**)&pcursor, d_cursor);
    cudaGetSymbolAddress((void**)&pcsrc, d_csrc);
    cudaGetSymbolAddress((void**)&pcsrw, d_csrw);
    cudaGetSymbolAddress((void**)&pbsum, d_bsum);

    cudaFuncSetAttribute(bf16x2_gemm_kernel<1, 0>,
                         cudaFuncAttributeMaxDynamicSharedMemorySize, GEMM_SMEM_BYTES);
    cudaFuncSetAttribute(bf16x2_gemm_kernel<0, 1>,
                         cudaFuncAttributeMaxDynamicSharedMemorySize, GEMM_SMEM_BYTES);

    // 0. zero deg + pooled accumulator
    zero_kernel<<<(NNODES + 255) / 256, 256>>>(pdeg, pG);
    // 1-3. build CSR-by-dst (parallel 3-phase scan)
    hist_kernel<<<(NEDGES + 255) / 256, 256>>>(edge_dst, pdeg);
    scan_blocks<<<NSCANB, 256>>>(pdeg, prptr, pbsum);
    scan_bsums<<<1, 256>>>(pbsum, prptr);
    add_offs<<<NSCANB, 256>>>(prptr, pbsum, pcursor);
    fill_kernel<<<(NEDGES + 255) / 256, 256>>>(edge_src, edge_dst, edge_w,
                                               pcursor, pcsrc, pcsrw);
    // 4. AX = A @ X   (spmm on the 128-wide input: spmm(x@W1) == spmm(x)@W1)
    {
        constexpr int NPB = 256 / (FIN / 4);   // 8 nodes / block
        spmm_csr_v4<FIN / 4><<<(NNODES + NPB - 1) / NPB, 256>>>(
            (const float4*)x, prptr, pcsrc, pcsrw, (float4*)pAX);
    }
    // 5. H1 = relu(AX @ W1 + b1)   [bf16x2 tensor cores, fp32 out]
    {
        dim3 grid((NNODES + 127) / 128, HID / 128);
        bf16x2_gemm_kernel<1, 0><<<grid, 256, GEMM_SMEM_BYTES>>>(
            pAX, W1, b1, pH1, nullptr, NNODES, HID, FIN);
    }
    // 6. T2 = H1 @ W2              [bf16x2 tensor cores, bf16 out]
    {
        dim3 grid((NNODES + 127) / 128, HID / 128);
        bf16x2_gemm_kernel<0, 1><<<grid, 256, GEMM_SMEM_BYTES>>>(
            pH1, W2, nullptr, nullptr, pT2, NNODES, HID, HID);
    }
    // 7. G[seg] += relu(spmm(T2) + b2)   [bf16 gathers, R14 geometry]
    {
        constexpr int NPB = 256 / (HID / 4);   // 4 nodes / block, grid 12500
        spmm_pool_bf16<<<(NNODES + NPB - 1) / NPB, 256>>>(
            (const uint2*)pT2, prptr, pcsrc, pcsrw, (const float4*)b2, seg_ids, pG);
    }
    // 8. head
    head_kernel<<<NGRAPH, HID>>>(pG, Wd, bd, Wo, bo, out);
}